// round 7
// baseline (speedup 1.0000x reference)
#include <cuda_runtime.h>
#include <cstdint>

// Problem constants
#define BB 256
#define SS 2048
#define TT 64
#define CH 4                  // chains per CTA (2 warps per chain, 8 warps)
#define NCTA (BB / CH)        // 64 CTAs
#define TILE 8                // steps per feats tile (2 KB per chain)
#define NBUF 4
#define NTILES (SS / TILE)    // 256

// Partial results: [0..255] = fwd per batch, [256..511] = -gold per batch
__device__ float g_partial[2 * BB];

// ---------------- dtype detection helpers ----------------
__device__ __forceinline__ int detect_mask_kind(const void* m) {
    unsigned u = *reinterpret_cast<const unsigned*>(m);
    if (u == 0x3f800000u) return 2;      // float 1.0
    if (u == 1u)          return 1;      // int32 1
    return 0;                             // packed bool bytes
}
__device__ __forceinline__ int mask_nz(const void* m, int kind, size_t i) {
    if (kind == 0) return reinterpret_cast<const unsigned char*>(m)[i] != 0;
    if (kind == 1) return reinterpret_cast<const int*>(m)[i] != 0;
    return reinterpret_cast<const float*>(m)[i] != 0.0f;
}
__device__ __forceinline__ bool detect_tags64(const void* t) {
    const int* p = reinterpret_cast<const int*>(t);
    bool all_hi_zero = true;
#pragma unroll
    for (int k = 0; k < 8; k++)
        if (p[2 * k + 1] != 0) all_hi_zero = false;
    return all_hi_zero;
}
__device__ __forceinline__ int tag_at(const void* t, bool is64, size_t i) {
    if (is64) return (int)reinterpret_cast<const long long*>(t)[i];
    return reinterpret_cast<const int*>(t)[i];
}

// ---------------- packed f32x2 helpers ----------------
__device__ __forceinline__ void fma2(unsigned long long& d,
                                     unsigned long long a, unsigned long long b) {
    asm("fma.rn.f32x2 %0, %1, %2, %0;" : "+l"(d) : "l"(a), "l"(b));
}
__device__ __forceinline__ unsigned long long add2(unsigned long long a,
                                                   unsigned long long b) {
    unsigned long long d;
    asm("add.rn.f32x2 %0, %1, %2;" : "=l"(d) : "l"(a), "l"(b));
    return d;
}
__device__ __forceinline__ unsigned long long pk2(float x, float y) {
    unsigned long long d;
    asm("mov.b64 %0, {%1, %2};" : "=l"(d) : "r"(__float_as_uint(x)), "r"(__float_as_uint(y)));
    return d;
}
__device__ __forceinline__ float hadd2(unsigned long long a) {
    unsigned lo, hi;
    asm("mov.b64 {%0,%1}, %2;" : "=r"(lo), "=r"(hi) : "l"(a));
    return __uint_as_float(lo) + __uint_as_float(hi);
}

// ---------------- forward (log-partition) kernel ----------------
// 4 chains per CTA, 2 warps per chain (8 warps): each SMSP hosts TWO
// independent chains, so one chain's barrier/dependency bubbles are filled
// by the other chain's FMA stream (R6 profile: issue was only 33%).
// Warp sw of a chain owns states j in [32sw, 32sw+32); lane owns ONE state j,
// summing all 64 i with 32 packed FMA2 + 16 broadcast LDS.128. Chain-private
// named barrier (64 threads) once per step. Linear-domain recurrence with
// lag-1 power-of-2 rescale posted via smem by the state-0 lane (exact math).
// feats staged with a per-chain cp.async tile pipeline, 2 tiles ahead.
__global__ void __launch_bounds__(256)
crf_fwd_kernel(const float* __restrict__ feats,
               const float* __restrict__ trans,
               const float* __restrict__ startt,
               const float* __restrict__ endt,
               const void* __restrict__ mask) {
    __shared__ __align__(16) float sf[CH][NBUF][TILE * TT];   // 32 KB
    __shared__ __align__(16) float wbuf[CH][2][TT];           // 2 KB
    __shared__ float sscale[CH][2];
    __shared__ float sred[CH][2];

    const int tid  = threadIdx.x;
    const int wid  = tid >> 5;
    const int l    = tid & 31;
    const int ch   = wid >> 1;         // chain within CTA (0..3)
    const int sw   = wid & 1;          // sub-warp within chain
    const int wtid = (sw << 5) + l;    // 0..63 within chain
    const int b    = blockIdx.x * CH + ch;
    const int j    = (sw << 5) + l;    // this lane's state
    const int barid = 1 + ch;          // named barrier per chain (1..4)
    const float* fb = feats + (size_t)b * SS * TT;

    auto chain_bar = [&]() {
        asm volatile("bar.sync %0, 64;" :: "r"(barid) : "memory");
    };

    // per-chain cp.async tile loader: tile k covers steps [k*TILE, k*TILE+TILE)
    auto issue_tile = [&](int k) {
        if (k < NTILES) {
            const char* src = reinterpret_cast<const char*>(fb)
                              + (size_t)k * TILE * TT * 4 + wtid * 32;
            unsigned dst = (unsigned)__cvta_generic_to_shared(
                reinterpret_cast<char*>(&sf[ch][k & (NBUF - 1)][0]) + wtid * 32);
            asm volatile("cp.async.ca.shared.global [%0], [%1], 16;"
                         :: "r"(dst), "l"(src));
            asm volatile("cp.async.ca.shared.global [%0], [%1], 16;"
                         :: "r"(dst + 16), "l"(src + 16));
        }
        asm volatile("cp.async.commit_group;");
    };

    issue_tile(0);
    issue_tile(1);
    issue_tile(2);

    // ---- sequence length (mask is a prefix), warp-local ----
    const int mk = detect_mask_kind(mask);
    int L;
    {
        int c = 0;
        const size_t base = (size_t)b * SS;
        for (int t = l; t < SS; t += 32) c += mask_nz(mask, mk, base + t);
#pragma unroll
        for (int o = 16; o; o >>= 1) c += __shfl_xor_sync(0xffffffffu, c, o);
        L = c;
    }

    // ---- E column j in registers, packed over i-pairs ----
    unsigned long long E[32];
#pragma unroll
    for (int k = 0; k < 32; k++) {
        float ea = trans[(2 * k) * TT + j];
        float eb = trans[(2 * k + 1) * TT + j];
        E[k] = pk2(__expf(ea), __expf(eb));
    }

    // ---- init w(0), sscale ----
    wbuf[ch][0][j] = __expf(startt[j] + fb[j]);
    if (wtid == 0) { sscale[ch][0] = 1.0f; sscale[ch][1] = 1.0f; }
    int e_cur = 0, LS = 0;     // meaningful on the state-0 lane only

    asm volatile("cp.async.wait_group 2;" ::: "memory");
    chain_bar();

    // one recurrence step: reads rb (w at t-1), writes wb (w at t).
    auto stepfn = [&](int t, const float* rb, float* wb) {
        float scale = sscale[ch][(t + 1) & 1];     // posted at t-1 (lag-1)
        float fg = sf[ch][(t >> 3) & (NBUF - 1)][((t & (TILE - 1)) << 6) + j];
        float g = exp2f(fg * 1.44269504f);

        const ulonglong2* wv = reinterpret_cast<const ulonglong2*>(rb);
        unsigned long long a0 = 0ull, a1 = 0ull, a2 = 0ull, a3 = 0ull;
#pragma unroll
        for (int q = 0; q < 8; q++) {
            ulonglong2 v1 = wv[2 * q];
            ulonglong2 v2 = wv[2 * q + 1];
            fma2(a0, v1.x, E[4 * q + 0]);
            fma2(a1, v1.y, E[4 * q + 1]);
            fma2(a2, v2.x, E[4 * q + 2]);
            fma2(a3, v2.y, E[4 * q + 3]);
        }
        float s = hadd2(add2(add2(a0, a1), add2(a2, a3)));

        wb[j] = s * (g * scale);

        if (wtid == 0) {                            // state-0 lane tracks scale
            LS += e_cur;
            e_cur = ((__float_as_int(s) >> 23) & 255) - 127;
            sscale[ch][t & 1] = __int_as_float((127 - e_cur) << 23);
        }
        chain_bar();
    };

    // ---- main recurrence, 2x unrolled (t starts odd -> refill check only on
    //      the even step; buffer parities static per half) ----
    float* w0 = wbuf[ch][0];
    float* w1 = wbuf[ch][1];
    int t = 1;
    for (; t + 1 < L; t += 2) {
        stepfn(t, w0, w1);                          // t odd: never a tile edge
        int tn = t + 1;
        if ((tn & (TILE - 1)) == 0) {
            int k = tn >> 3;
            issue_tile(k + 2);
            asm volatile("cp.async.wait_group 2;" ::: "memory");
            chain_bar();
        }
        stepfn(tn, w1, w0);
    }
    if (t < L) stepfn(t, w0, w1);

    // ---- final logsumexp with end transitions ----
    {
        float v = wbuf[ch][(L - 1) & 1][j] * __expf(endt[j]);
#pragma unroll
        for (int o = 16; o; o >>= 1) v += __shfl_down_sync(0xffffffffu, v, o);
        if (l == 0) sred[ch][sw] = v;
        chain_bar();
        if (wtid == 0)
            g_partial[b] = logf(sred[ch][0] + sred[ch][1])
                         + (float)LS * 0.693147180559945309f;
    }
    asm volatile("cp.async.wait_group 0;" ::: "memory");
}

// ---------------- gold (path score) kernel ----------------
__global__ void __launch_bounds__(256)
crf_gold_kernel(const float* __restrict__ feats,
                const float* __restrict__ trans,
                const float* __restrict__ startt,
                const float* __restrict__ endt,
                const void* __restrict__ tags,
                const void* __restrict__ mask) {
    __shared__ float swr[8];
    __shared__ int   swc[8];

    const int b   = blockIdx.x;
    const int tid = threadIdx.x;
    const int mk  = detect_mask_kind(mask);
    const bool t64 = detect_tags64(tags);
    const size_t base = (size_t)b * SS;

    float acc = 0.f;
    int   cnt = 0;
    for (int t = tid; t < SS; t += 256) {
        int m0 = mask_nz(mask, mk, base + t);
        cnt += m0;
        if (t < SS - 1) {
            int tg  = tag_at(tags, t64, base + t);
            int tg1 = tag_at(tags, t64, base + t + 1);
            int m1  = mask_nz(mask, mk, base + t + 1);
            float em = feats[(base + (size_t)t) * TT + tg];
            float tr = trans[tg * TT + tg1];
            acc += tr * (float)m1 + em * (float)m0;
        }
    }
#pragma unroll
    for (int o = 16; o; o >>= 1) {
        acc += __shfl_down_sync(0xffffffffu, acc, o);
        cnt += __shfl_down_sync(0xffffffffu, cnt, o);
    }
    if ((tid & 31) == 0) { swr[tid >> 5] = acc; swc[tid >> 5] = cnt; }
    __syncthreads();
    if (tid == 0) {
        float a = 0.f; int L = 0;
#pragma unroll
        for (int ww = 0; ww < 8; ww++) { a += swr[ww]; L += swc[ww]; }
        int first = tag_at(tags, t64, base);
        int last  = tag_at(tags, t64, base + L - 1);
        float gold = a + startt[first] + endt[last];
        if (mask_nz(mask, mk, base + SS - 1))
            gold += feats[(base + (size_t)(SS - 1)) * TT + last];
        g_partial[BB + b] = -gold;
    }
}

// ---------------- deterministic final reduction ----------------
__global__ void __launch_bounds__(256)
crf_reduce_kernel(float* __restrict__ out) {
    __shared__ float sred[8];
    int tid = threadIdx.x;
    float v = g_partial[tid] + g_partial[tid + BB];
#pragma unroll
    for (int o = 16; o; o >>= 1) v += __shfl_down_sync(0xffffffffu, v, o);
    if ((tid & 31) == 0) sred[tid >> 5] = v;
    __syncthreads();
    if (tid == 0) {
        float tot = 0.f;
#pragma unroll
        for (int ww = 0; ww < 8; ww++) tot += sred[ww];
        out[0] = tot;
    }
}

extern "C" void kernel_launch(void* const* d_in, const int* in_sizes, int n_in,
                              void* d_out, int out_size) {
    const float* feats  = (const float*)d_in[0];
    const float* trans  = (const float*)d_in[1];
    const float* startt = (const float*)d_in[2];
    const float* endt   = (const float*)d_in[3];
    const void*  tags   = d_in[4];
    const void*  mask   = d_in[5];
    float* out = (float*)d_out;

    crf_fwd_kernel<<<NCTA, 256>>>(feats, trans, startt, endt, mask);
    crf_gold_kernel<<<BB, 256>>>(feats, trans, startt, endt, tags, mask);
    crf_reduce_kernel<<<1, 256>>>(out);
}

// round 8
// speedup vs baseline: 1.2946x; 1.2946x over previous
#include <cuda_runtime.h>
#include <cstdint>

// Problem constants
#define BB 256
#define SS 2048
#define TT 64
#define CH 2                   // chains per CTA (2 warps per chain)
#define NFWD (BB / CH)         // 128 fwd CTAs
#define NGOLD 32               // gold CTAs (co-resident on free SMs)
#define GB (BB / NGOLD)        // batches per gold CTA = 8
#define TILE 16                // steps per feats tile (4 KB per chain)
#define NBUF 4
#define NTILES (SS / TILE)     // 128

// Partial results: [0..255] = fwd per batch, [256..511] = -gold per batch
__device__ float g_partial[2 * BB];

// ---------------- dtype detection helpers ----------------
__device__ __forceinline__ int detect_mask_kind(const void* m) {
    unsigned u = *reinterpret_cast<const unsigned*>(m);
    if (u == 0x3f800000u) return 2;      // float 1.0
    if (u == 1u)          return 1;      // int32 1
    return 0;                             // packed bool bytes
}
__device__ __forceinline__ int mask_nz(const void* m, int kind, size_t i) {
    if (kind == 0) return reinterpret_cast<const unsigned char*>(m)[i] != 0;
    if (kind == 1) return reinterpret_cast<const int*>(m)[i] != 0;
    return reinterpret_cast<const float*>(m)[i] != 0.0f;
}
__device__ __forceinline__ bool detect_tags64(const void* t) {
    const int* p = reinterpret_cast<const int*>(t);
    bool all_hi_zero = true;
#pragma unroll
    for (int k = 0; k < 8; k++)
        if (p[2 * k + 1] != 0) all_hi_zero = false;
    return all_hi_zero;
}
__device__ __forceinline__ int tag_at(const void* t, bool is64, size_t i) {
    if (is64) return (int)reinterpret_cast<const long long*>(t)[i];
    return reinterpret_cast<const int*>(t)[i];
}

// ---------------- packed f32x2 helpers ----------------
__device__ __forceinline__ void fma2(unsigned long long& d,
                                     unsigned long long a, unsigned long long b) {
    asm("fma.rn.f32x2 %0, %1, %2, %0;" : "+l"(d) : "l"(a), "l"(b));
}
__device__ __forceinline__ unsigned long long add2(unsigned long long a,
                                                   unsigned long long b) {
    unsigned long long d;
    asm("add.rn.f32x2 %0, %1, %2;" : "=l"(d) : "l"(a), "l"(b));
    return d;
}
__device__ __forceinline__ unsigned long long pk2(float x, float y) {
    unsigned long long d;
    asm("mov.b64 %0, {%1, %2};" : "=l"(d) : "r"(__float_as_uint(x)), "r"(__float_as_uint(y)));
    return d;
}
__device__ __forceinline__ float hadd2(unsigned long long a) {
    unsigned lo, hi;
    asm("mov.b64 {%0,%1}, %2;" : "=r"(lo), "=r"(hi) : "l"(a));
    return __uint_as_float(lo) + __uint_as_float(hi);
}

// ---------------- gold path score (device function, 128 threads) ----------------
__device__ void gold_one_batch(const float* __restrict__ feats,
                               const float* __restrict__ trans,
                               const float* __restrict__ startt,
                               const float* __restrict__ endt,
                               const void* __restrict__ tags,
                               const void* __restrict__ mask,
                               int b, int mk, bool t64,
                               float* swr, int* swc) {
    const int tid = threadIdx.x;
    const size_t base = (size_t)b * SS;

    float acc = 0.f;
    int   cnt = 0;
    for (int t = tid; t < SS; t += 128) {
        int m0 = mask_nz(mask, mk, base + t);
        cnt += m0;
        if (t < SS - 1) {
            int tg  = tag_at(tags, t64, base + t);
            int tg1 = tag_at(tags, t64, base + t + 1);
            int m1  = mask_nz(mask, mk, base + t + 1);
            float em = feats[(base + (size_t)t) * TT + tg];
            float tr = trans[tg * TT + tg1];
            acc += tr * (float)m1 + em * (float)m0;
        }
    }
#pragma unroll
    for (int o = 16; o; o >>= 1) {
        acc += __shfl_down_sync(0xffffffffu, acc, o);
        cnt += __shfl_down_sync(0xffffffffu, cnt, o);
    }
    if ((tid & 31) == 0) { swr[tid >> 5] = acc; swc[tid >> 5] = cnt; }
    __syncthreads();
    if (tid == 0) {
        float a = 0.f; int L = 0;
#pragma unroll
        for (int ww = 0; ww < 4; ww++) { a += swr[ww]; L += swc[ww]; }
        int first = tag_at(tags, t64, base);
        int last  = tag_at(tags, t64, base + L - 1);
        float gold = a + startt[first] + endt[last];
        if (mask_nz(mask, mk, base + SS - 1))
            gold += feats[(base + (size_t)(SS - 1)) * TT + last];
        g_partial[BB + b] = -gold;
    }
    __syncthreads();
}

// ---------------- fused forward + gold kernel ----------------
// CTAs [0,128): forward recurrence, 2 chains per CTA, 2 warps per chain
//   (R6 layout: 1 warp/SMSP across 128 SMs — max spread, proven best).
// CTAs [128,160): gold path scores, 8 batches each, co-resident on the ~20
//   free SMs -> fully hidden under the forward wall time.
__global__ void __launch_bounds__(128)
crf_fused_kernel(const float* __restrict__ feats,
                 const float* __restrict__ trans,
                 const float* __restrict__ startt,
                 const float* __restrict__ endt,
                 const void* __restrict__ tags,
                 const void* __restrict__ mask) {
    __shared__ __align__(16) float sf[CH][NBUF][TILE * TT];   // 32 KB
    __shared__ __align__(16) float wbuf[CH][2][TT];           // 1 KB
    __shared__ float sscale[CH][2];
    __shared__ float sred[CH][2];

    const int mk = detect_mask_kind(mask);

    if (blockIdx.x >= NFWD) {
        // -------- gold CTAs --------
        const bool t64 = detect_tags64(tags);
        float* swr = (float*)&sred[0][0];            // reuse smem (4 floats ok)
        __shared__ int swc4[4];
        int bbase = (blockIdx.x - NFWD) * GB;
        for (int q = 0; q < GB; q++)
            gold_one_batch(feats, trans, startt, endt, tags, mask,
                           bbase + q, mk, t64, swr, swc4);
        return;
    }

    // -------- forward CTAs --------
    const int tid  = threadIdx.x;
    const int wid  = tid >> 5;
    const int l    = tid & 31;
    const int ch   = wid >> 1;         // chain within CTA
    const int sw   = wid & 1;          // sub-warp within chain
    const int wtid = (sw << 5) + l;    // 0..63 within chain
    const int b    = blockIdx.x * CH + ch;
    const int j    = (sw << 5) + l;    // this lane's state
    const int barid = 1 + ch;          // named barrier per chain
    const float* fb = feats + (size_t)b * SS * TT;

    auto chain_bar = [&]() {
        asm volatile("bar.sync %0, 64;" :: "r"(barid) : "memory");
    };

    // per-chain cp.async tile loader: tile k covers steps [k*TILE, (k+1)*TILE)
    auto issue_tile = [&](int k) {
        if (k < NTILES) {
            const char* src = reinterpret_cast<const char*>(fb)
                              + (size_t)k * TILE * TT * 4 + wtid * 64;
            unsigned dst = (unsigned)__cvta_generic_to_shared(
                reinterpret_cast<char*>(&sf[ch][k & (NBUF - 1)][0]) + wtid * 64);
#pragma unroll
            for (int c = 0; c < 4; c++)
                asm volatile("cp.async.ca.shared.global [%0], [%1], 16;"
                             :: "r"(dst + 16 * c), "l"(src + 16 * c));
        }
        asm volatile("cp.async.commit_group;");
    };

    issue_tile(0);
    issue_tile(1);
    issue_tile(2);

    // ---- sequence length (mask is a prefix), warp-local ----
    int L;
    {
        int c = 0;
        const size_t base = (size_t)b * SS;
        for (int t = l; t < SS; t += 32) c += mask_nz(mask, mk, base + t);
#pragma unroll
        for (int o = 16; o; o >>= 1) c += __shfl_xor_sync(0xffffffffu, c, o);
        L = c;
    }

    // ---- E column j in registers, packed over i-pairs ----
    unsigned long long E[32];
#pragma unroll
    for (int k = 0; k < 32; k++) {
        float ea = trans[(2 * k) * TT + j];
        float eb = trans[(2 * k + 1) * TT + j];
        E[k] = pk2(__expf(ea), __expf(eb));
    }

    // ---- init w(0), sscale ----
    wbuf[ch][0][j] = __expf(startt[j] + fb[j]);
    if (wtid == 0) { sscale[ch][0] = 1.0f; sscale[ch][1] = 1.0f; }
    int e_cur = 0, LS = 0;     // meaningful on the state-0 lane only

    asm volatile("cp.async.wait_group 2;" ::: "memory");
    chain_bar();

    // one recurrence step: reads rb (w at t-1), writes wb (w at t).
    auto stepfn = [&](int t, const float* rb, float* wb) {
        float scale = sscale[ch][(t + 1) & 1];     // posted at t-1 (lag-1)
        float fg = sf[ch][(t >> 4) & (NBUF - 1)][((t & (TILE - 1)) << 6) + j];
        float g = __expf(fg);

        const ulonglong2* wv = reinterpret_cast<const ulonglong2*>(rb);
        unsigned long long a0 = 0ull, a1 = 0ull, a2 = 0ull, a3 = 0ull;
#pragma unroll
        for (int q = 0; q < 8; q++) {
            ulonglong2 v1 = wv[2 * q];
            ulonglong2 v2 = wv[2 * q + 1];
            fma2(a0, v1.x, E[4 * q + 0]);
            fma2(a1, v1.y, E[4 * q + 1]);
            fma2(a2, v2.x, E[4 * q + 2]);
            fma2(a3, v2.y, E[4 * q + 3]);
        }
        float s = hadd2(add2(add2(a0, a1), add2(a2, a3)));

        wb[j] = s * (g * scale);

        if (wtid == 0) {                            // state-0 lane tracks scale
            LS += e_cur;
            e_cur = ((__float_as_int(s) >> 23) & 255) - 127;
            sscale[ch][t & 1] = __int_as_float((127 - e_cur) << 23);
        }
        chain_bar();
    };

    // ---- main recurrence, 2x unrolled; tile edges only on even steps ----
    float* w0 = wbuf[ch][0];
    float* w1 = wbuf[ch][1];
    int t = 1;
    for (; t + 1 < L; t += 2) {
        stepfn(t, w0, w1);                          // t odd: never a tile edge
        int tn = t + 1;
        if ((tn & (TILE - 1)) == 0) {
            int k = tn >> 4;
            issue_tile(k + 2);
            asm volatile("cp.async.wait_group 2;" ::: "memory");
            chain_bar();
        }
        stepfn(tn, w1, w0);
    }
    if (t < L) stepfn(t, w0, w1);

    // ---- final logsumexp with end transitions ----
    {
        float v = wbuf[ch][(L - 1) & 1][j] * __expf(endt[j]);
#pragma unroll
        for (int o = 16; o; o >>= 1) v += __shfl_down_sync(0xffffffffu, v, o);
        if (l == 0) sred[ch][sw] = v;
        chain_bar();
        if (wtid == 0)
            g_partial[b] = logf(sred[ch][0] + sred[ch][1])
                         + (float)LS * 0.693147180559945309f;
    }
    asm volatile("cp.async.wait_group 0;" ::: "memory");
}

// ---------------- deterministic final reduction ----------------
__global__ void __launch_bounds__(256)
crf_reduce_kernel(float* __restrict__ out) {
    __shared__ float sred[8];
    int tid = threadIdx.x;
    float v = g_partial[tid] + g_partial[tid + BB];
#pragma unroll
    for (int o = 16; o; o >>= 1) v += __shfl_down_sync(0xffffffffu, v, o);
    if ((tid & 31) == 0) sred[tid >> 5] = v;
    __syncthreads();
    if (tid == 0) {
        float tot = 0.f;
#pragma unroll
        for (int ww = 0; ww < 8; ww++) tot += sred[ww];
        out[0] = tot;
    }
}

extern "C" void kernel_launch(void* const* d_in, const int* in_sizes, int n_in,
                              void* d_out, int out_size) {
    const float* feats  = (const float*)d_in[0];
    const float* trans  = (const float*)d_in[1];
    const float* startt = (const float*)d_in[2];
    const float* endt   = (const float*)d_in[3];
    const void*  tags   = d_in[4];
    const void*  mask   = d_in[5];
    float* out = (float*)d_out;

    crf_fused_kernel<<<NFWD + NGOLD, 128>>>(feats, trans, startt, endt, tags, mask);
    crf_reduce_kernel<<<1, 256>>>(out);
}

// round 9
// speedup vs baseline: 1.8522x; 1.4307x over previous
#include <cuda_runtime.h>
#include <cstdint>

// Problem constants
#define BB 256
#define SS 2048
#define TT 64
#define CH 2                   // chains per CTA (2 warps per chain)
#define NFWD (BB / CH)         // 128 fwd CTAs
#define NGOLD 20               // gold CTAs -> grid = 148 = #SMs exactly
#define GB 13                  // batches per gold CTA (20*13 >= 256)
#define TILE 16                // steps per feats tile (4 KB per chain)
#define NBUF 4
#define NTILES (SS / TILE)     // 128

// Partial results: [0..255] = fwd per batch, [256..511] = -gold per batch
__device__ float g_partial[2 * BB];

// ---------------- dtype detection helpers ----------------
__device__ __forceinline__ int detect_mask_kind(const void* m) {
    unsigned u = *reinterpret_cast<const unsigned*>(m);
    if (u == 0x3f800000u) return 2;      // float 1.0
    if (u == 1u)          return 1;      // int32 1
    return 0;                             // packed bool bytes
}
__device__ __forceinline__ int mask_nz(const void* m, int kind, size_t i) {
    if (kind == 0) return reinterpret_cast<const unsigned char*>(m)[i] != 0;
    if (kind == 1) return reinterpret_cast<const int*>(m)[i] != 0;
    return reinterpret_cast<const float*>(m)[i] != 0.0f;
}
__device__ __forceinline__ bool detect_tags64(const void* t) {
    const int* p = reinterpret_cast<const int*>(t);
    bool all_hi_zero = true;
#pragma unroll
    for (int k = 0; k < 8; k++)
        if (p[2 * k + 1] != 0) all_hi_zero = false;
    return all_hi_zero;
}
__device__ __forceinline__ int tag_at(const void* t, bool is64, size_t i) {
    if (is64) return (int)reinterpret_cast<const long long*>(t)[i];
    return reinterpret_cast<const int*>(t)[i];
}

// ---------------- packed f32x2 helpers ----------------
__device__ __forceinline__ void fma2(unsigned long long& d,
                                     unsigned long long a, unsigned long long b) {
    asm("fma.rn.f32x2 %0, %1, %2, %0;" : "+l"(d) : "l"(a), "l"(b));
}
__device__ __forceinline__ unsigned long long add2(unsigned long long a,
                                                   unsigned long long b) {
    unsigned long long d;
    asm("add.rn.f32x2 %0, %1, %2;" : "=l"(d) : "l"(a), "l"(b));
    return d;
}
__device__ __forceinline__ unsigned long long pk2(float x, float y) {
    unsigned long long d;
    asm("mov.b64 %0, {%1, %2};" : "=l"(d) : "r"(__float_as_uint(x)), "r"(__float_as_uint(y)));
    return d;
}
__device__ __forceinline__ float hadd2(unsigned long long a) {
    unsigned lo, hi;
    asm("mov.b64 {%0,%1}, %2;" : "=r"(lo), "=r"(hi) : "l"(a));
    return __uint_as_float(lo) + __uint_as_float(hi);
}

// ---------------- gold path score (device function, 128 threads) ----------------
__device__ void gold_one_batch(const float* __restrict__ feats,
                               const float* __restrict__ trans,
                               const float* __restrict__ startt,
                               const float* __restrict__ endt,
                               const void* __restrict__ tags,
                               const void* __restrict__ mask,
                               int b, int mk, bool t64,
                               float* swr, int* swc) {
    const int tid = threadIdx.x;
    const size_t base = (size_t)b * SS;

    float acc = 0.f;
    int   cnt = 0;
    for (int t = tid; t < SS; t += 128) {
        int m0 = mask_nz(mask, mk, base + t);
        cnt += m0;
        if (t < SS - 1) {
            int tg  = tag_at(tags, t64, base + t);
            int tg1 = tag_at(tags, t64, base + t + 1);
            int m1  = mask_nz(mask, mk, base + t + 1);
            float em = feats[(base + (size_t)t) * TT + tg];
            float tr = trans[tg * TT + tg1];
            acc += tr * (float)m1 + em * (float)m0;
        }
    }
#pragma unroll
    for (int o = 16; o; o >>= 1) {
        acc += __shfl_down_sync(0xffffffffu, acc, o);
        cnt += __shfl_down_sync(0xffffffffu, cnt, o);
    }
    if ((tid & 31) == 0) { swr[tid >> 5] = acc; swc[tid >> 5] = cnt; }
    __syncthreads();
    if (tid == 0) {
        float a = 0.f; int L = 0;
#pragma unroll
        for (int ww = 0; ww < 4; ww++) { a += swr[ww]; L += swc[ww]; }
        int first = tag_at(tags, t64, base);
        int last  = tag_at(tags, t64, base + L - 1);
        float gold = a + startt[first] + endt[last];
        if (mask_nz(mask, mk, base + SS - 1))
            gold += feats[(base + (size_t)(SS - 1)) * TT + last];
        g_partial[BB + b] = -gold;
    }
    __syncthreads();
}

// ---------------- fused forward + gold kernel (grid = 148 = #SMs) ----------------
// CTAs [0,128): forward recurrence — 2 chains/CTA, 2 warps/chain, 1 warp/SMSP
//   (the only layout that hasn't regressed; R7/R8 proved co-residency kills it).
// CTAs [128,148): gold path scores on the 20 otherwise-idle SMs.
// Forward step sync uses split bar.arrive/bar.sync so the next step's
// emission LDS+exp overlaps the barrier wait.
__global__ void __launch_bounds__(128)
crf_fused_kernel(const float* __restrict__ feats,
                 const float* __restrict__ trans,
                 const float* __restrict__ startt,
                 const float* __restrict__ endt,
                 const void* __restrict__ tags,
                 const void* __restrict__ mask) {
    __shared__ __align__(16) float sf[CH][NBUF][TILE * TT];   // 32 KB
    __shared__ __align__(16) float wbuf[CH][2][TT];           // 1 KB
    __shared__ float sscale[CH][2];
    __shared__ float sred[CH][2];

    const int mk = detect_mask_kind(mask);

    if (blockIdx.x >= NFWD) {
        // -------- gold CTAs --------
        const bool t64 = detect_tags64(tags);
        __shared__ float swr4[4];
        __shared__ int   swc4[4];
        int bbase = (blockIdx.x - NFWD) * GB;
        int bend  = bbase + GB; if (bend > BB) bend = BB;
        for (int q = bbase; q < bend; q++)
            gold_one_batch(feats, trans, startt, endt, tags, mask,
                           q, mk, t64, swr4, swc4);
        return;
    }

    // -------- forward CTAs --------
    const int tid  = threadIdx.x;
    const int wid  = tid >> 5;
    const int l    = tid & 31;
    const int ch   = wid >> 1;         // chain within CTA
    const int sw   = wid & 1;          // sub-warp within chain
    const int wtid = (sw << 5) + l;    // 0..63 within chain
    const int b    = blockIdx.x * CH + ch;
    const int j    = (sw << 5) + l;    // this lane's state
    const int barid = 1 + ch;          // named barrier per chain
    const float* fb = feats + (size_t)b * SS * TT;

    // split-barrier primitives: 64 arrives + 64 syncs = 128 per phase
    auto bar_arrive = [&]() {
        asm volatile("bar.arrive %0, 128;" :: "r"(barid) : "memory");
    };
    auto bar_wait = [&]() {
        asm volatile("bar.sync %0, 128;" :: "r"(barid) : "memory");
    };

    // per-chain cp.async tile loader: tile k covers steps [k*TILE, (k+1)*TILE)
    auto issue_tile = [&](int k) {
        if (k < NTILES) {
            const char* src = reinterpret_cast<const char*>(fb)
                              + (size_t)k * TILE * TT * 4 + wtid * 64;
            unsigned dst = (unsigned)__cvta_generic_to_shared(
                reinterpret_cast<char*>(&sf[ch][k & (NBUF - 1)][0]) + wtid * 64);
#pragma unroll
            for (int c = 0; c < 4; c++)
                asm volatile("cp.async.ca.shared.global [%0], [%1], 16;"
                             :: "r"(dst + 16 * c), "l"(src + 16 * c));
        }
        asm volatile("cp.async.commit_group;");
    };

    // prefill 4 tiles; at edge k we issue k+3 and wait to <=2 pending,
    // guaranteeing tiles <= k+1 resident (cross-tile prefetch needs k+1).
    issue_tile(0);
    issue_tile(1);
    issue_tile(2);
    issue_tile(3);

    // ---- sequence length (mask is a prefix), warp-local ----
    int L;
    {
        int c = 0;
        const size_t base = (size_t)b * SS;
        for (int t = l; t < SS; t += 32) c += mask_nz(mask, mk, base + t);
#pragma unroll
        for (int o = 16; o; o >>= 1) c += __shfl_xor_sync(0xffffffffu, c, o);
        L = c;
    }

    // ---- E column j in registers, packed over i-pairs ----
    unsigned long long E[32];
#pragma unroll
    for (int k = 0; k < 32; k++) {
        float ea = trans[(2 * k) * TT + j];
        float eb = trans[(2 * k + 1) * TT + j];
        E[k] = pk2(__expf(ea), __expf(eb));
    }

    // ---- init w(0), sscale ----
    wbuf[ch][0][j] = __expf(startt[j] + fb[j]);
    if (wtid == 0) { sscale[ch][0] = 1.0f; sscale[ch][1] = 1.0f; }
    int e_cur = 0, LS = 0;     // meaningful on the state-0 lane only

    asm volatile("cp.async.wait_group 2;" ::: "memory");  // tiles 0,1 done (own)
    bar_arrive(); bar_wait();          // full barrier: publish init + tiles

    // emission factor for step 1 (tile 0 resident & published)
    float g = __expf(sf[ch][0][(1 << 6) + j]);

    bar_arrive();                      // open phase for step 1's sync

    // ---- main recurrence ----
    for (int t = 1; t < L; t++) {
        if ((t & (TILE - 1)) == 0) {
            issue_tile((t >> 4) + 3);
            asm volatile("cp.async.wait_group 2;" ::: "memory");
        }
        bar_wait();                                   // w(t-1), scale published

        float scale = sscale[ch][(t + 1) & 1];        // posted at t-1 (lag-1)

        const ulonglong2* wv =
            reinterpret_cast<const ulonglong2*>(wbuf[ch][(t + 1) & 1]);
        unsigned long long a0 = 0ull, a1 = 0ull, a2 = 0ull, a3 = 0ull;
#pragma unroll
        for (int q = 0; q < 8; q++) {
            ulonglong2 v1 = wv[2 * q];
            ulonglong2 v2 = wv[2 * q + 1];
            fma2(a0, v1.x, E[4 * q + 0]);
            fma2(a1, v1.y, E[4 * q + 1]);
            fma2(a2, v2.x, E[4 * q + 2]);
            fma2(a3, v2.y, E[4 * q + 3]);
        }
        float s = hadd2(add2(add2(a0, a1), add2(a2, a3)));

        wbuf[ch][t & 1][j] = s * (g * scale);

        if (wtid == 0) {                              // state-0 lane tracks scale
            LS += e_cur;
            e_cur = ((__float_as_int(s) >> 23) & 255) - 127;
            sscale[ch][t & 1] = __int_as_float((127 - e_cur) << 23);
        }
        bar_arrive();

        // post-arrive window: prefetch next emission (overlaps barrier wait)
        int tn = t + 1;
        g = __expf(sf[ch][(tn >> 4) & (NBUF - 1)][((tn & (TILE - 1)) << 6) + j]);
    }

    // ---- final logsumexp with end transitions ----
    {
        float v = wbuf[ch][(L - 1) & 1][j] * __expf(endt[j]);
#pragma unroll
        for (int o = 16; o; o >>= 1) v += __shfl_down_sync(0xffffffffu, v, o);
        if (l == 0) sred[ch][sw] = v;
        bar_wait();                                   // pairs with last arrive
        if (wtid == 0)
            g_partial[b] = logf(sred[ch][0] + sred[ch][1])
                         + (float)LS * 0.693147180559945309f;
    }
    asm volatile("cp.async.wait_group 0;" ::: "memory");
}

// ---------------- deterministic final reduction ----------------
__global__ void __launch_bounds__(256)
crf_reduce_kernel(float* __restrict__ out) {
    __shared__ float sred[8];
    int tid = threadIdx.x;
    float v = g_partial[tid] + g_partial[tid + BB];
#pragma unroll
    for (int o = 16; o; o >>= 1) v += __shfl_down_sync(0xffffffffu, v, o);
    if ((tid & 31) == 0) sred[tid >> 5] = v;
    __syncthreads();
    if (tid == 0) {
        float tot = 0.f;
#pragma unroll
        for (int ww = 0; ww < 8; ww++) tot += sred[ww];
        out[0] = tot;
    }
}

extern "C" void kernel_launch(void* const* d_in, const int* in_sizes, int n_in,
                              void* d_out, int out_size) {
    const float* feats  = (const float*)d_in[0];
    const float* trans  = (const float*)d_in[1];
    const float* startt = (const float*)d_in[2];
    const float* endt   = (const float*)d_in[3];
    const void*  tags   = d_in[4];
    const void*  mask   = d_in[5];
    float* out = (float*)d_out;

    crf_fused_kernel<<<NFWD + NGOLD, 128>>>(feats, trans, startt, endt, tags, mask);
    crf_reduce_kernel<<<1, 256>>>(out);
}

// round 10
// speedup vs baseline: 2.2099x; 1.1931x over previous
#include <cuda_runtime.h>
#include <cstdint>

// Problem constants
#define BB 256
#define SS 2048
#define TT 64
#define CH 2                   // chains per CTA (2 warps per chain)
#define NFWD (BB / CH)         // 128 fwd CTAs
#define NGOLD 20               // gold CTAs -> grid = 148 = #SMs exactly
#define GB 13                  // batches per gold CTA (20*13 >= 256)
#define TILE 8                 // steps per feats tile (2 KB per chain)
#define NBUF 4
#define NTILES (SS / TILE)     // 256

// Partial results: [0..255] = fwd per batch, [256..511] = -gold per batch
__device__ float g_partial[2 * BB];

// ---------------- dtype detection helpers ----------------
__device__ __forceinline__ int detect_mask_kind(const void* m) {
    unsigned u = *reinterpret_cast<const unsigned*>(m);
    if (u == 0x3f800000u) return 2;      // float 1.0
    if (u == 1u)          return 1;      // int32 1
    return 0;                             // packed bool bytes
}
__device__ __forceinline__ int mask_nz(const void* m, int kind, size_t i) {
    if (kind == 0) return reinterpret_cast<const unsigned char*>(m)[i] != 0;
    if (kind == 1) return reinterpret_cast<const int*>(m)[i] != 0;
    return reinterpret_cast<const float*>(m)[i] != 0.0f;
}
__device__ __forceinline__ bool detect_tags64(const void* t) {
    const int* p = reinterpret_cast<const int*>(t);
    bool all_hi_zero = true;
#pragma unroll
    for (int k = 0; k < 8; k++)
        if (p[2 * k + 1] != 0) all_hi_zero = false;
    return all_hi_zero;
}
__device__ __forceinline__ int tag_at(const void* t, bool is64, size_t i) {
    if (is64) return (int)reinterpret_cast<const long long*>(t)[i];
    return reinterpret_cast<const int*>(t)[i];
}

// ---------------- packed f32x2 helpers ----------------
__device__ __forceinline__ void fma2(unsigned long long& d,
                                     unsigned long long a, unsigned long long b) {
    asm("fma.rn.f32x2 %0, %1, %2, %0;" : "+l"(d) : "l"(a), "l"(b));
}
__device__ __forceinline__ unsigned long long add2(unsigned long long a,
                                                   unsigned long long b) {
    unsigned long long d;
    asm("add.rn.f32x2 %0, %1, %2;" : "=l"(d) : "l"(a), "l"(b));
    return d;
}
__device__ __forceinline__ unsigned long long pk2(float x, float y) {
    unsigned long long d;
    asm("mov.b64 %0, {%1, %2};" : "=l"(d) : "r"(__float_as_uint(x)), "r"(__float_as_uint(y)));
    return d;
}
__device__ __forceinline__ float hadd2(unsigned long long a) {
    unsigned lo, hi;
    asm("mov.b64 {%0,%1}, %2;" : "=r"(lo), "=r"(hi) : "l"(a));
    return __uint_as_float(lo) + __uint_as_float(hi);
}

// ---------------- gold path score (device function, 128 threads) ----------------
__device__ void gold_one_batch(const float* __restrict__ feats,
                               const float* __restrict__ trans,
                               const float* __restrict__ startt,
                               const float* __restrict__ endt,
                               const void* __restrict__ tags,
                               const void* __restrict__ mask,
                               int b, int mk, bool t64,
                               float* swr, int* swc) {
    const int tid = threadIdx.x;
    const size_t base = (size_t)b * SS;

    float acc = 0.f;
    int   cnt = 0;
    for (int t = tid; t < SS; t += 128) {
        int m0 = mask_nz(mask, mk, base + t);
        cnt += m0;
        if (t < SS - 1) {
            int tg  = tag_at(tags, t64, base + t);
            int tg1 = tag_at(tags, t64, base + t + 1);
            int m1  = mask_nz(mask, mk, base + t + 1);
            float em = feats[(base + (size_t)t) * TT + tg];
            float tr = trans[tg * TT + tg1];
            acc += tr * (float)m1 + em * (float)m0;
        }
    }
#pragma unroll
    for (int o = 16; o; o >>= 1) {
        acc += __shfl_down_sync(0xffffffffu, acc, o);
        cnt += __shfl_down_sync(0xffffffffu, cnt, o);
    }
    if ((tid & 31) == 0) { swr[tid >> 5] = acc; swc[tid >> 5] = cnt; }
    __syncthreads();
    if (tid == 0) {
        float a = 0.f; int L = 0;
#pragma unroll
        for (int ww = 0; ww < 4; ww++) { a += swr[ww]; L += swc[ww]; }
        int first = tag_at(tags, t64, base);
        int last  = tag_at(tags, t64, base + L - 1);
        float gold = a + startt[first] + endt[last];
        if (mask_nz(mask, mk, base + SS - 1))
            gold += feats[(base + (size_t)(SS - 1)) * TT + last];
        g_partial[BB + b] = -gold;
    }
    __syncthreads();
}

// ---------------- fused forward + gold kernel (grid = 148 = #SMs) ----------------
// CTAs [0,128): forward recurrence — R6's proven step engine VERBATIM
//   (2 chains/CTA, 2 warps/chain, plain bar.sync 64, TILE 8, lag-1 rescale).
// CTAs [128,148): gold path scores on the 20 otherwise-idle SMs (hidden).
__global__ void __launch_bounds__(128)
crf_fused_kernel(const float* __restrict__ feats,
                 const float* __restrict__ trans,
                 const float* __restrict__ startt,
                 const float* __restrict__ endt,
                 const void* __restrict__ tags,
                 const void* __restrict__ mask) {
    __shared__ __align__(16) float sf[CH][NBUF][TILE * TT];   // 16 KB
    __shared__ __align__(16) float wbuf[CH][2][TT];           // 1 KB
    __shared__ float sscale[CH][2];
    __shared__ float sred[CH][2];

    const int mk = detect_mask_kind(mask);

    if (blockIdx.x >= NFWD) {
        // -------- gold CTAs --------
        const bool t64 = detect_tags64(tags);
        __shared__ float swr4[4];
        __shared__ int   swc4[4];
        int bbase = (blockIdx.x - NFWD) * GB;
        int bend  = bbase + GB; if (bend > BB) bend = BB;
        for (int q = bbase; q < bend; q++)
            gold_one_batch(feats, trans, startt, endt, tags, mask,
                           q, mk, t64, swr4, swc4);
        return;
    }

    // -------- forward CTAs (R6 verbatim) --------
    const int tid  = threadIdx.x;
    const int wid  = tid >> 5;
    const int l    = tid & 31;
    const int ch   = wid >> 1;         // chain within CTA
    const int sw   = wid & 1;          // sub-warp within chain
    const int wtid = (sw << 5) + l;    // 0..63 within chain
    const int b    = blockIdx.x * CH + ch;
    const int j    = (sw << 5) + l;    // this lane's state
    const int barid = 1 + ch;          // named barrier per chain
    const float* fb = feats + (size_t)b * SS * TT;

    auto chain_bar = [&]() {
        asm volatile("bar.sync %0, 64;" :: "r"(barid) : "memory");
    };

    // per-chain cp.async tile loader: tile k covers steps [k*TILE, k*TILE+TILE)
    auto issue_tile = [&](int k) {
        if (k < NTILES) {
            const char* src = reinterpret_cast<const char*>(fb)
                              + (size_t)k * TILE * TT * 4 + wtid * 32;
            unsigned dst = (unsigned)__cvta_generic_to_shared(
                reinterpret_cast<char*>(&sf[ch][k & (NBUF - 1)][0]) + wtid * 32);
            asm volatile("cp.async.ca.shared.global [%0], [%1], 16;"
                         :: "r"(dst), "l"(src));
            asm volatile("cp.async.ca.shared.global [%0], [%1], 16;"
                         :: "r"(dst + 16), "l"(src + 16));
        }
        asm volatile("cp.async.commit_group;");
    };

    issue_tile(0);
    issue_tile(1);
    issue_tile(2);

    // ---- sequence length (mask is a prefix), warp-local ----
    int L;
    {
        int c = 0;
        const size_t base = (size_t)b * SS;
        for (int t = l; t < SS; t += 32) c += mask_nz(mask, mk, base + t);
#pragma unroll
        for (int o = 16; o; o >>= 1) c += __shfl_xor_sync(0xffffffffu, c, o);
        L = c;
    }

    // ---- E column j in registers, packed over i-pairs ----
    unsigned long long E[32];
#pragma unroll
    for (int k = 0; k < 32; k++) {
        float ea = trans[(2 * k) * TT + j];
        float eb = trans[(2 * k + 1) * TT + j];
        E[k] = pk2(__expf(ea), __expf(eb));
    }

    // ---- init w(0), sscale ----
    wbuf[ch][0][j] = __expf(startt[j] + fb[j]);
    if (wtid == 0) { sscale[ch][0] = 1.0f; sscale[ch][1] = 1.0f; }
    int e_cur = 0, LS = 0;     // meaningful on the state-0 lane only

    asm volatile("cp.async.wait_group 2;" ::: "memory");
    chain_bar();

    // ---- main recurrence: one named barrier per step ----
    for (int t = 1; t < L; t++) {
        if ((t & (TILE - 1)) == 0) {
            int k = t >> 3;
            issue_tile(k + 2);
            asm volatile("cp.async.wait_group 2;" ::: "memory");
            chain_bar();
        }

        // lag-1 scale (posted at step t-1) + emission factor (early loads)
        float scale = sscale[ch][(t + 1) & 1];
        float fg = sf[ch][(t >> 3) & (NBUF - 1)][((t & (TILE - 1)) << 6) + j];
        float g = exp2f(fg * 1.44269504f);

        // row j of the matvec: 32 packed FMA2 over broadcast w (16 LDS.128)
        const ulonglong2* wv =
            reinterpret_cast<const ulonglong2*>(wbuf[ch][(t + 1) & 1]);
        unsigned long long a0 = 0ull, a1 = 0ull, a2 = 0ull, a3 = 0ull;
#pragma unroll
        for (int q = 0; q < 8; q++) {
            ulonglong2 v1 = wv[2 * q];
            ulonglong2 v2 = wv[2 * q + 1];
            fma2(a0, v1.x, E[4 * q + 0]);
            fma2(a1, v1.y, E[4 * q + 1]);
            fma2(a2, v2.x, E[4 * q + 2]);
            fma2(a3, v2.y, E[4 * q + 3]);
        }
        float s = hadd2(add2(add2(a0, a1), add2(a2, a3)));

        wbuf[ch][t & 1][j] = s * (g * scale);

        // scale-exponent tracker: state 0 lives on warp0-lane0; lag-1 post
        if (wtid == 0) {
            LS += e_cur;
            e_cur = ((__float_as_int(s) >> 23) & 255) - 127;
            sscale[ch][t & 1] = __int_as_float((127 - e_cur) << 23);
        }
        chain_bar();
    }

    // ---- final logsumexp with end transitions ----
    {
        float v = wbuf[ch][(L - 1) & 1][j] * __expf(endt[j]);
#pragma unroll
        for (int o = 16; o; o >>= 1) v += __shfl_down_sync(0xffffffffu, v, o);
        if (l == 0) sred[ch][sw] = v;
        chain_bar();
        if (wtid == 0)
            g_partial[b] = logf(sred[ch][0] + sred[ch][1])
                         + (float)LS * 0.693147180559945309f;
    }
    asm volatile("cp.async.wait_group 0;" ::: "memory");
}

// ---------------- deterministic final reduction ----------------
__global__ void __launch_bounds__(256)
crf_reduce_kernel(float* __restrict__ out) {
    __shared__ float sred[8];
    int tid = threadIdx.x;
    float v = g_partial[tid] + g_partial[tid + BB];
#pragma unroll
    for (int o = 16; o; o >>= 1) v += __shfl_down_sync(0xffffffffu, v, o);
    if ((tid & 31) == 0) sred[tid >> 5] = v;
    __syncthreads();
    if (tid == 0) {
        float tot = 0.f;
#pragma unroll
        for (int ww = 0; ww < 8; ww++) tot += sred[ww];
        out[0] = tot;
    }
}

extern "C" void kernel_launch(void* const* d_in, const int* in_sizes, int n_in,
                              void* d_out, int out_size) {
    const float* feats  = (const float*)d_in[0];
    const float* trans  = (const float*)d_in[1];
    const float* startt = (const float*)d_in[2];
    const float* endt   = (const float*)d_in[3];
    const void*  tags   = d_in[4];
    const void*  mask   = d_in[5];
    float* out = (float*)d_out;

    crf_fused_kernel<<<NFWD + NGOLD, 128>>>(feats, trans, startt, endt, tags, mask);
    crf_reduce_kernel<<<1, 256>>>(out);
}